// round 12
// baseline (speedup 1.0000x reference)
#include <cuda_runtime.h>
#include <cstdint>
#include <math.h>

// Problem shape (fixed): B=4, H=8, S=1024, D=64
#define SLEN 1024
#define HD   64
#define NBH  32
#define NROWS (NBH * SLEN)           // 32768
#define NTOT  ((size_t)NROWS * SLEN) // 33554432 = 2^25
#define NBINS 4096                   // bits >> 18 : 8 exp + 5 mantissa bits

typedef unsigned long long ull;

// ---------------- scratch ---------------------------------------------------
__device__ float g_score[NROWS * SLEN];          // 128 MiB raw scores
__device__ unsigned int g_hist[NBINS];           // 16 KiB counts
__device__ float g_ttab[NBINS + 1];              // edge t values
__device__ float g_invq[NROWS];
__device__ float g_invk[NROWS];

// ---------------- f32x2 helpers (sm_103a) -----------------------------------
__device__ __forceinline__ ull pack2(float a, float b) {
    ull r; asm("mov.b64 %0, {%1,%2};" : "=l"(r) : "f"(a), "f"(b)); return r;
}
__device__ __forceinline__ ull fma2(ull a, ull b, ull c) {
    ull d; asm("fma.rn.f32x2 %0, %1, %2, %3;" : "=l"(d) : "l"(a), "l"(b), "l"(c));
    return d;
}
__device__ __forceinline__ float2 unpack2(ull v) {
    float2 f; asm("mov.b64 {%0,%1}, %2;" : "=f"(f.x), "=f"(f.y) : "l"(v));
    return f;
}
__device__ __forceinline__ unsigned sw(unsigned a) {      // 128B-line swizzle
    return a ^ ((a >> 3) & 0x70u);
}

// ---------------- kernel 1: inverse row norms (+ hist zeroing) --------------
__global__ __launch_bounds__(256) void norms_kernel(const float* __restrict__ Q,
                                                    const float* __restrict__ K) {
    if (blockIdx.x < 16) g_hist[blockIdx.x * 256 + threadIdx.x] = 0u;
    int w = (blockIdx.x * 256 + threadIdx.x) >> 5;
    int lane = threadIdx.x & 31;
    const float* src; float* dst; int row;
    if (w < NROWS) { src = Q; dst = g_invq; row = w; }
    else           { src = K; dst = g_invk; row = w - NROWS; }
    const float* p = src + (size_t)row * HD;
    float a = p[lane], b = p[lane + 32];
    float s = a * a + b * b;
    #pragma unroll
    for (int o = 16; o; o >>= 1) s += __shfl_xor_sync(0xffffffffu, s, o);
    if (lane == 0) dst[row] = 1.0f / (sqrtf(s) + 1e-5f);
}

// ---------------- kernel 2: score GEMM + smem-private histogram -------------
// (unchanged from best-known score: k-major A staging, lane-parity subhists)
__global__ __launch_bounds__(256, 2) void score_kernel(const float* __restrict__ Q,
                                                       const float* __restrict__ K) {
    __shared__ __align__(16) float Qsk[32 * 132];  // [k][row] (hist0 alias)
    __shared__ __align__(16) float Ks[32 * 128];   // k-major SW128 (hist1 alias)
    int bh = blockIdx.z;
    int i0 = blockIdx.y * 128, j0 = blockIdx.x * 128;
    const float* Qb = Q + (size_t)bh * SLEN * HD;
    const float* Kb = K + (size_t)bh * SLEN * HD;
    int tid = threadIdx.x;
    int tx = tid & 15, ty = tid >> 4;

    ull acc[8][4];
    #pragma unroll
    for (int ii = 0; ii < 8; ii++)
        #pragma unroll
        for (int p = 0; p < 4; p++) acc[ii][p] = 0ull;

    #pragma unroll
    for (int c = 0; c < 2; c++) {          // k chunks of 32 (ascending order!)
        int k0 = c * 32;
        if (c) __syncthreads();
        #pragma unroll
        for (int pass = 0; pass < 4; pass++) {
            int row = (tid >> 3) + pass * 32;
            int kq = (tid & 7) * 4;
            float4 q4 = *(const float4*)&Qb[(i0 + row) * HD + k0 + kq];
            Qsk[(kq + 0) * 132 + row] = q4.x;
            Qsk[(kq + 1) * 132 + row] = q4.y;
            Qsk[(kq + 2) * 132 + row] = q4.z;
            Qsk[(kq + 3) * 132 + row] = q4.w;
            float4 k4 = *(const float4*)&Kb[(j0 + row) * HD + k0 + kq];
            #pragma unroll
            for (int e = 0; e < 4; e++) {
                unsigned a = (unsigned)(kq + e) * 512u + (unsigned)row * 4u;
                Ks[sw(a) >> 2] = (&k4.x)[e];
            }
        }
        __syncthreads();
        #pragma unroll
        for (int k = 0; k < 32; k++) {
            unsigned a0 = (unsigned)k * 512u + (unsigned)tx * 32u;
            float4 b0 = *(const float4*)&Ks[sw(a0) >> 2];
            float4 b1 = *(const float4*)&Ks[sw(a0 + 16u) >> 2];
            ull bv0 = pack2(b0.x, b0.y), bv1 = pack2(b0.z, b0.w);
            ull bv2 = pack2(b1.x, b1.y), bv3 = pack2(b1.z, b1.w);
            float4 av0 = *(const float4*)&Qsk[k * 132 + ty * 8];
            float4 av1 = *(const float4*)&Qsk[k * 132 + ty * 8 + 4];
            const float* avp0 = &av0.x;
            const float* avp1 = &av1.x;
            #pragma unroll
            for (int ii = 0; ii < 4; ii++) {
                ull a2 = pack2(avp0[ii], avp0[ii]);
                acc[ii][0] = fma2(a2, bv0, acc[ii][0]);
                acc[ii][1] = fma2(a2, bv1, acc[ii][1]);
                acc[ii][2] = fma2(a2, bv2, acc[ii][2]);
                acc[ii][3] = fma2(a2, bv3, acc[ii][3]);
            }
            #pragma unroll
            for (int ii = 0; ii < 4; ii++) {
                ull a2 = pack2(avp1[ii], avp1[ii]);
                acc[4 + ii][0] = fma2(a2, bv0, acc[4 + ii][0]);
                acc[4 + ii][1] = fma2(a2, bv1, acc[4 + ii][1]);
                acc[4 + ii][2] = fma2(a2, bv2, acc[4 + ii][2]);
                acc[4 + ii][3] = fma2(a2, bv3, acc[4 + ii][3]);
            }
        }
    }

    // ---- epilogue: tiles dead; alias as two u16-packed lane-parity subhists --
    unsigned* hist0 = (unsigned*)Qsk;     // 2048 u32 = 4096 u16 counters
    unsigned* hist1 = (unsigned*)Ks;      // 2048 u32
    __syncthreads();
    for (int i = tid; i < 2048; i += 256) { hist0[i] = 0u; hist1[i] = 0u; }
    __syncthreads();
    unsigned* hsel = (tid & 1) ? hist1 : hist0;

    int jb = j0 + tx * 8;
    float ikv[8];
    #pragma unroll
    for (int jj = 0; jj < 8; jj++) ikv[jj] = g_invk[bh * SLEN + jb + jj];
    #pragma unroll
    for (int ii = 0; ii < 8; ii++) {
        int row = bh * SLEN + i0 + ty * 8 + ii;
        float iq = g_invq[row];
        float2 c0 = unpack2(acc[ii][0]);
        float2 c1 = unpack2(acc[ii][1]);
        float2 c2 = unpack2(acc[ii][2]);
        float2 c3 = unpack2(acc[ii][3]);
        float v[8];
        v[0] = c0.x * iq * ikv[0]; v[1] = c0.y * iq * ikv[1];
        v[2] = c1.x * iq * ikv[2]; v[3] = c1.y * iq * ikv[3];
        v[4] = c2.x * iq * ikv[4]; v[5] = c2.y * iq * ikv[5];
        v[6] = c3.x * iq * ikv[6]; v[7] = c3.y * iq * ikv[7];
        size_t idx = (size_t)row * SLEN + jb;
        *(float4*)&g_score[idx]     = make_float4(v[0], v[1], v[2], v[3]);
        *(float4*)&g_score[idx + 4] = make_float4(v[4], v[5], v[6], v[7]);
        #pragma unroll
        for (int e = 0; e < 8; e++) {
            unsigned bin = __float_as_uint(fabsf(v[e])) >> 18;   // < 4096
            atomicAdd(&hsel[bin >> 1], 1u << ((bin & 1u) * 16u));
        }
    }

    __syncthreads();
    for (int i = tid; i < 2048; i += 256) {
        unsigned p0 = hist0[i], p1 = hist1[i];
        unsigned lo = (p0 & 0xFFFFu) + (p1 & 0xFFFFu);
        unsigned hi = (p0 >> 16) + (p1 >> 16);
        if (lo) atomicAdd(&g_hist[2 * i],     lo);
        if (hi) atomicAdd(&g_hist[2 * i + 1], hi);
    }
}

// ---------------- kernel 2.5: scan 4096 bins + edge t table (1 block) -------
__global__ __launch_bounds__(1024) void scan_ttab_kernel() {
    __shared__ unsigned ws[32];
    int tid = threadIdx.x;
    int lane = tid & 31, wid = tid >> 5;
    unsigned c0 = g_hist[tid * 4], c1 = g_hist[tid * 4 + 1];
    unsigned c2 = g_hist[tid * 4 + 2], c3 = g_hist[tid * 4 + 3];
    unsigned tsum = c0 + c1 + c2 + c3;
    unsigned incl = tsum;
    #pragma unroll
    for (int o = 1; o < 32; o <<= 1) {
        unsigned n = __shfl_up_sync(0xffffffffu, incl, o);
        if (lane >= o) incl += n;
    }
    if (lane == 31) ws[wid] = incl;
    __syncthreads();
    if (wid == 0) {
        unsigned v = ws[lane];
        #pragma unroll
        for (int o = 1; o < 32; o <<= 1) {
            unsigned n = __shfl_up_sync(0xffffffffu, v, o);
            if (lane >= o) v += n;
        }
        ws[lane] = v;
    }
    __syncthreads();
    unsigned excl = incl - tsum + (wid ? ws[wid - 1] : 0u);
    const float sA = 1.0f / 33554431.0f;   // 1/(n-1)
    const float sB = 1.0f / 33554432.0f;   // 1/n
    unsigned e0 = excl, e1 = e0 + c0, e2 = e1 + c1, e3 = e2 + c2;
    g_ttab[tid * 4]     = -__logf(fmaf((float)e0, sA, sB));
    g_ttab[tid * 4 + 1] = -__logf(fmaf((float)e1, sA, sB));
    g_ttab[tid * 4 + 2] = -__logf(fmaf((float)e2, sA, sB));
    g_ttab[tid * 4 + 3] = -__logf(fmaf((float)e3, sA, sB));
    if (tid == 1023)
        g_ttab[4096] = -__logf(fmaf((float)(e3 + c3), sA, sB));
}

// ---------------- kernel 3: fused transform + rowsum + out GEMM --------------
// 1024 blocks x 32 rows. Small tiles -> acc[4] (low regs) -> 4 blocks/SM.
// Register double-buffer: next chunk's P (1 float4/thread) and V (2 float4)
// are prefetched before the math phase, hiding LDG latency under the FMAs.
__global__ __launch_bounds__(256) void out_kernel(const float* __restrict__ V,
                                                  float* __restrict__ O) {
    __shared__ float Ts[32 * 33];        // [row][k] t values (4.2 KB)
    __shared__ float Vs[32 * 64];        // [k][d] SW128 (8 KB)
    __shared__ float ttab_s[NBINS + 1];  // 16.4 KB
    __shared__ float spart[256];
    __shared__ float sinv[32];

    int blk = blockIdx.x;                // 0..1023
    int bh = blk >> 5;
    int i0 = blk * 32;                   // global row base
    const float* Vb = V + (size_t)bh * SLEN * HD;
    int tid = threadIdx.x;
    int tx = tid & 7, ty = tid >> 3;     // math: tx d-group (8 cols), ty = row
    int prow = ty, pcol = tx * 4;        // staging: 8 threads per row, 4 cols each
    int kv = ty, d8 = tx * 8;            // V staging: thread stages row kv, 8 cols

    for (int i = tid; i < NBINS + 1; i += 256) ttab_s[i] = g_ttab[i];
    __syncthreads();                     // table must be complete before use!

    ull acc[4];
    acc[0] = acc[1] = acc[2] = acc[3] = 0ull;
    float srow = 0.0f;

    const float* prow_ptr = g_score + (size_t)(i0 + prow) * SLEN + pcol;
    const float* vrow_ptr = &Vb[kv * HD + d8];

    // prefetch chunk 0
    float4 pv  = *(const float4*)prow_ptr;
    float4 vv0 = *(const float4*)vrow_ptr;
    float4 vv1 = *(const float4*)(vrow_ptr + 4);

    for (int c = 0; c < 32; c++) {
        if (c) __syncthreads();          // math of c-1 done before overwrite
        // consume prefetched V -> Vs (swizzled)
        {
            unsigned a = (unsigned)kv * 256u + (unsigned)d8 * 4u;
            *(float4*)&Vs[sw(a) >> 2]       = vv0;
            *(float4*)&Vs[sw(a + 16u) >> 2] = vv1;
        }
        // consume prefetched P -> transform -> Ts; accumulate partial row sum
        {
            float* td = &Ts[prow * 33 + pcol];
            #pragma unroll
            for (int e = 0; e < 4; e++) {
                float v = (&pv.x)[e];
                unsigned bits = __float_as_uint(fabsf(v));
                unsigned b = bits >> 18;
                float frac = (float)(bits & 0x3FFFFu) * (1.0f / 262144.0f);
                float t0 = ttab_s[b], t1 = ttab_s[b + 1];
                float t = fmaf(frac, t1 - t0, t0);
                t = (v > 0.0f) ? t : ((v < 0.0f) ? -t : 0.0f);
                srow += fabsf(t);
                td[e] = t;
            }
        }
        // prefetch chunk c+1 (uniform branch)
        if (c < 31) {
            pv  = *(const float4*)(prow_ptr + (c + 1) * 32);
            const float* vp = vrow_ptr + (size_t)(c + 1) * 32 * HD;
            vv0 = *(const float4*)vp;
            vv1 = *(const float4*)(vp + 4);
        }
        __syncthreads();
        // math: acc += Ts[ty][k] * Vs[k][tx*8..+8]
        #pragma unroll
        for (int k = 0; k < 32; k++) {
            unsigned a0 = (unsigned)k * 256u + (unsigned)tx * 32u;
            float4 b0 = *(const float4*)&Vs[sw(a0) >> 2];
            float4 b1 = *(const float4*)&Vs[sw(a0 + 16u) >> 2];
            float av = Ts[ty * 33 + k];
            ull a2 = pack2(av, av);
            acc[0] = fma2(a2, pack2(b0.x, b0.y), acc[0]);
            acc[1] = fma2(a2, pack2(b0.z, b0.w), acc[1]);
            acc[2] = fma2(a2, pack2(b1.x, b1.y), acc[2]);
            acc[3] = fma2(a2, pack2(b1.z, b1.w), acc[3]);
        }
    }

    spart[tid] = srow;
    __syncthreads();
    if (tid < 32) {
        float s = 0.0f;
        #pragma unroll
        for (int j = 0; j < 8; j++) s += spart[tid * 8 + j];
        sinv[tid] = 1.0f / s;
    }
    __syncthreads();

    float s = sinv[ty];
    float2 c0 = unpack2(acc[0]);
    float2 c1 = unpack2(acc[1]);
    float2 c2 = unpack2(acc[2]);
    float2 c3 = unpack2(acc[3]);
    size_t oidx = (size_t)(i0 + ty) * HD + tx * 8;
    *(float4*)&O[oidx]     = make_float4(c0.x * s, c0.y * s, c1.x * s, c1.y * s);
    *(float4*)&O[oidx + 4] = make_float4(c2.x * s, c2.y * s, c3.x * s, c3.y * s);
}

// ---------------- launcher ---------------------------------------------------
extern "C" void kernel_launch(void* const* d_in, const int* in_sizes, int n_in,
                              void* d_out, int out_size) {
    const float* Q = (const float*)d_in[0];
    const float* K = (const float*)d_in[1];
    const float* V = (const float*)d_in[2];
    float* O = (float*)d_out;

    norms_kernel<<<8192, 256>>>(Q, K);
    score_kernel<<<dim3(8, 8, NBH), 256>>>(Q, K);
    scan_ttab_kernel<<<1, 1024>>>();
    out_kernel<<<1024, 256>>>(V, O);
}

// round 14
// speedup vs baseline: 1.4447x; 1.4447x over previous
#include <cuda_runtime.h>
#include <cstdint>
#include <math.h>

// Problem shape (fixed): B=4, H=8, S=1024, D=64
#define SLEN 1024
#define HD   64
#define NBH  32
#define NROWS (NBH * SLEN)           // 32768
#define NTOT  ((size_t)NROWS * SLEN) // 33554432 = 2^25
#define NBINS 4096                   // bits >> 18 : 8 exp + 5 mantissa bits

typedef unsigned long long ull;

// ---------------- scratch ---------------------------------------------------
__device__ float g_score[NROWS * SLEN];          // 128 MiB raw scores
__device__ unsigned int g_hist[NBINS];           // 16 KiB counts
__device__ float g_ttab[NBINS + 1];              // edge t values
__device__ float g_invq[NROWS];
__device__ float g_invk[NROWS];

// ---------------- f32x2 helpers (sm_103a) -----------------------------------
__device__ __forceinline__ ull pack2(float a, float b) {
    ull r; asm("mov.b64 %0, {%1,%2};" : "=l"(r) : "f"(a), "f"(b)); return r;
}
__device__ __forceinline__ ull fma2(ull a, ull b, ull c) {
    ull d; asm("fma.rn.f32x2 %0, %1, %2, %3;" : "=l"(d) : "l"(a), "l"(b), "l"(c));
    return d;
}
__device__ __forceinline__ float2 unpack2(ull v) {
    float2 f; asm("mov.b64 {%0,%1}, %2;" : "=f"(f.x), "=f"(f.y) : "l"(v));
    return f;
}
__device__ __forceinline__ unsigned sw(unsigned a) {      // 128B-line swizzle
    return a ^ ((a >> 3) & 0x70u);
}

// ---------------- kernel 1: inverse row norms (+ hist zeroing) --------------
__global__ __launch_bounds__(256) void norms_kernel(const float* __restrict__ Q,
                                                    const float* __restrict__ K) {
    if (blockIdx.x < 16) g_hist[blockIdx.x * 256 + threadIdx.x] = 0u;
    int w = (blockIdx.x * 256 + threadIdx.x) >> 5;
    int lane = threadIdx.x & 31;
    const float* src; float* dst; int row;
    if (w < NROWS) { src = Q; dst = g_invq; row = w; }
    else           { src = K; dst = g_invk; row = w - NROWS; }
    const float* p = src + (size_t)row * HD;
    float a = p[lane], b = p[lane + 32];
    float s = a * a + b * b;
    #pragma unroll
    for (int o = 16; o; o >>= 1) s += __shfl_xor_sync(0xffffffffu, s, o);
    if (lane == 0) dst[row] = 1.0f / (sqrtf(s) + 1e-5f);
}

// ---------------- kernel 2: score GEMM + smem-private histogram -------------
__global__ __launch_bounds__(256, 2) void score_kernel(const float* __restrict__ Q,
                                                       const float* __restrict__ K) {
    __shared__ __align__(16) float Qsk[32 * 132];  // [k][row] (hist0 alias)
    __shared__ __align__(16) float Ks[32 * 128];   // k-major SW128 (hist1 alias)
    int bh = blockIdx.z;
    int i0 = blockIdx.y * 128, j0 = blockIdx.x * 128;
    const float* Qb = Q + (size_t)bh * SLEN * HD;
    const float* Kb = K + (size_t)bh * SLEN * HD;
    int tid = threadIdx.x;
    int tx = tid & 15, ty = tid >> 4;

    ull acc[8][4];
    #pragma unroll
    for (int ii = 0; ii < 8; ii++)
        #pragma unroll
        for (int p = 0; p < 4; p++) acc[ii][p] = 0ull;

    #pragma unroll
    for (int c = 0; c < 2; c++) {          // k chunks of 32 (ascending order!)
        int k0 = c * 32;
        if (c) __syncthreads();
        #pragma unroll
        for (int pass = 0; pass < 4; pass++) {
            int row = (tid >> 3) + pass * 32;
            int kq = (tid & 7) * 4;
            float4 q4 = *(const float4*)&Qb[(i0 + row) * HD + k0 + kq];
            Qsk[(kq + 0) * 132 + row] = q4.x;
            Qsk[(kq + 1) * 132 + row] = q4.y;
            Qsk[(kq + 2) * 132 + row] = q4.z;
            Qsk[(kq + 3) * 132 + row] = q4.w;
            float4 k4 = *(const float4*)&Kb[(j0 + row) * HD + k0 + kq];
            #pragma unroll
            for (int e = 0; e < 4; e++) {
                unsigned a = (unsigned)(kq + e) * 512u + (unsigned)row * 4u;
                Ks[sw(a) >> 2] = (&k4.x)[e];
            }
        }
        __syncthreads();
        #pragma unroll
        for (int k = 0; k < 32; k++) {
            unsigned a0 = (unsigned)k * 512u + (unsigned)tx * 32u;
            float4 b0 = *(const float4*)&Ks[sw(a0) >> 2];
            float4 b1 = *(const float4*)&Ks[sw(a0 + 16u) >> 2];
            ull bv0 = pack2(b0.x, b0.y), bv1 = pack2(b0.z, b0.w);
            ull bv2 = pack2(b1.x, b1.y), bv3 = pack2(b1.z, b1.w);
            float4 av0 = *(const float4*)&Qsk[k * 132 + ty * 8];
            float4 av1 = *(const float4*)&Qsk[k * 132 + ty * 8 + 4];
            const float* avp0 = &av0.x;
            const float* avp1 = &av1.x;
            #pragma unroll
            for (int ii = 0; ii < 4; ii++) {
                ull a2 = pack2(avp0[ii], avp0[ii]);
                acc[ii][0] = fma2(a2, bv0, acc[ii][0]);
                acc[ii][1] = fma2(a2, bv1, acc[ii][1]);
                acc[ii][2] = fma2(a2, bv2, acc[ii][2]);
                acc[ii][3] = fma2(a2, bv3, acc[ii][3]);
            }
            #pragma unroll
            for (int ii = 0; ii < 4; ii++) {
                ull a2 = pack2(avp1[ii], avp1[ii]);
                acc[4 + ii][0] = fma2(a2, bv0, acc[4 + ii][0]);
                acc[4 + ii][1] = fma2(a2, bv1, acc[4 + ii][1]);
                acc[4 + ii][2] = fma2(a2, bv2, acc[4 + ii][2]);
                acc[4 + ii][3] = fma2(a2, bv3, acc[4 + ii][3]);
            }
        }
    }

    // ---- epilogue: tiles dead; alias as two u16-packed lane-parity subhists --
    unsigned* hist0 = (unsigned*)Qsk;     // 2048 u32 = 4096 u16 counters
    unsigned* hist1 = (unsigned*)Ks;      // 2048 u32
    __syncthreads();
    for (int i = tid; i < 2048; i += 256) { hist0[i] = 0u; hist1[i] = 0u; }
    __syncthreads();
    unsigned* hsel = (tid & 1) ? hist1 : hist0;

    int jb = j0 + tx * 8;
    float ikv[8];
    #pragma unroll
    for (int jj = 0; jj < 8; jj++) ikv[jj] = g_invk[bh * SLEN + jb + jj];
    #pragma unroll
    for (int ii = 0; ii < 8; ii++) {
        int row = bh * SLEN + i0 + ty * 8 + ii;
        float iq = g_invq[row];
        float2 c0 = unpack2(acc[ii][0]);
        float2 c1 = unpack2(acc[ii][1]);
        float2 c2 = unpack2(acc[ii][2]);
        float2 c3 = unpack2(acc[ii][3]);
        float v[8];
        v[0] = c0.x * iq * ikv[0]; v[1] = c0.y * iq * ikv[1];
        v[2] = c1.x * iq * ikv[2]; v[3] = c1.y * iq * ikv[3];
        v[4] = c2.x * iq * ikv[4]; v[5] = c2.y * iq * ikv[5];
        v[6] = c3.x * iq * ikv[6]; v[7] = c3.y * iq * ikv[7];
        size_t idx = (size_t)row * SLEN + jb;
        *(float4*)&g_score[idx]     = make_float4(v[0], v[1], v[2], v[3]);
        *(float4*)&g_score[idx + 4] = make_float4(v[4], v[5], v[6], v[7]);
        #pragma unroll
        for (int e = 0; e < 8; e++) {
            unsigned bin = __float_as_uint(fabsf(v[e])) >> 18;   // < 4096
            atomicAdd(&hsel[bin >> 1], 1u << ((bin & 1u) * 16u));
        }
    }

    __syncthreads();
    for (int i = tid; i < 2048; i += 256) {
        unsigned p0 = hist0[i], p1 = hist1[i];
        unsigned lo = (p0 & 0xFFFFu) + (p1 & 0xFFFFu);
        unsigned hi = (p0 >> 16) + (p1 >> 16);
        if (lo) atomicAdd(&g_hist[2 * i],     lo);
        if (hi) atomicAdd(&g_hist[2 * i + 1], hi);
    }
}

// ---------------- kernel 2.5: scan 4096 bins + edge t table (1 block) -------
__global__ __launch_bounds__(1024) void scan_ttab_kernel() {
    __shared__ unsigned ws[32];
    int tid = threadIdx.x;
    int lane = tid & 31, wid = tid >> 5;
    unsigned c0 = g_hist[tid * 4], c1 = g_hist[tid * 4 + 1];
    unsigned c2 = g_hist[tid * 4 + 2], c3 = g_hist[tid * 4 + 3];
    unsigned tsum = c0 + c1 + c2 + c3;
    unsigned incl = tsum;
    #pragma unroll
    for (int o = 1; o < 32; o <<= 1) {
        unsigned n = __shfl_up_sync(0xffffffffu, incl, o);
        if (lane >= o) incl += n;
    }
    if (lane == 31) ws[wid] = incl;
    __syncthreads();
    if (wid == 0) {
        unsigned v = ws[lane];
        #pragma unroll
        for (int o = 1; o < 32; o <<= 1) {
            unsigned n = __shfl_up_sync(0xffffffffu, v, o);
            if (lane >= o) v += n;
        }
        ws[lane] = v;
    }
    __syncthreads();
    unsigned excl = incl - tsum + (wid ? ws[wid - 1] : 0u);
    const float sA = 1.0f / 33554431.0f;   // 1/(n-1)
    const float sB = 1.0f / 33554432.0f;   // 1/n
    unsigned e0 = excl, e1 = e0 + c0, e2 = e1 + c1, e3 = e2 + c2;
    g_ttab[tid * 4]     = -__logf(fmaf((float)e0, sA, sB));
    g_ttab[tid * 4 + 1] = -__logf(fmaf((float)e1, sA, sB));
    g_ttab[tid * 4 + 2] = -__logf(fmaf((float)e2, sA, sB));
    g_ttab[tid * 4 + 3] = -__logf(fmaf((float)e3, sA, sB));
    if (tid == 1023)
        g_ttab[4096] = -__logf(fmaf((float)(e3 + c3), sA, sB));
}

// ---------------- kernel 3: fused transform + rowsum + out GEMM --------------
// 256 blocks x 128 rows, 4 rows x 8 cols per math thread (1.5 B LDS per MAC).
// Staging: warp w stages rows {w, w+8, ..., w+120}, lane = col (coalesced),
// in two 8-row batches. Row L1 sums are accumulated by the MATH threads from
// the Ts values they already read (tx==0 writes). 3 blocks/SM co-residency.
__global__ __launch_bounds__(256, 3) void out_kernel(const float* __restrict__ V,
                                                     float* __restrict__ O) {
    __shared__ float Ts[128 * 33];       // [row][k], staging conflict-free (16.5 KB)
    __shared__ float Vs[32 * 64];        // [k][d] SW128 (8 KB)
    __shared__ float ttab_s[NBINS + 1];  // 16.4 KB
    __shared__ float sinv[128];

    int blk = blockIdx.x;                // 0..255
    int bh = blk >> 3;
    int i0 = blk * 128;
    const float* Vb = V + (size_t)bh * SLEN * HD;
    int tid = threadIdx.x;
    int tx = tid & 7, ty = tid >> 3;     // math: 8 col-groups x 32 row-groups
    int lane = tid & 31, wrp = tid >> 5;
    int kv = tid >> 3, d8 = (tid & 7) * 8;   // V staging map

    for (int i = tid; i < NBINS + 1; i += 256) ttab_s[i] = g_ttab[i];
    __syncthreads();

    ull acc[4][4];
    #pragma unroll
    for (int ii = 0; ii < 4; ii++)
        #pragma unroll
        for (int p = 0; p < 4; p++) acc[ii][p] = 0ull;
    float srow4[4] = {0.0f, 0.0f, 0.0f, 0.0f};

    const float* pbase = g_score + (size_t)i0 * SLEN + lane;  // + row*SLEN + c*32
    const float* vrow_ptr = &Vb[kv * HD + d8];

    // prefetch V chunk 0
    float4 vv0 = *(const float4*)vrow_ptr;
    float4 vv1 = *(const float4*)(vrow_ptr + 4);

    for (int c = 0; c < 32; c++) {
        if (c) __syncthreads();          // previous math done before overwrite
        // consume prefetched V -> Vs (swizzled)
        {
            unsigned a = (unsigned)kv * 256u + (unsigned)d8 * 4u;
            *(float4*)&Vs[sw(a) >> 2]       = vv0;
            *(float4*)&Vs[sw(a + 16u) >> 2] = vv1;
        }
        // stage + transform P: rows wrp + r*8, col = c*32 + lane; 2 batches of 8
        #pragma unroll
        for (int hb = 0; hb < 2; hb++) {
            float v[8];
            #pragma unroll
            for (int r = 0; r < 8; r++) {
                int row = wrp + (hb * 8 + r) * 8;
                v[r] = __ldg(pbase + (size_t)row * SLEN + c * 32);
            }
            #pragma unroll
            for (int r = 0; r < 8; r++) {
                int row = wrp + (hb * 8 + r) * 8;
                float x = v[r];
                unsigned bits = __float_as_uint(fabsf(x));
                unsigned b = bits >> 18;
                float frac = (float)(bits & 0x3FFFFu) * (1.0f / 262144.0f);
                float t0 = ttab_s[b], t1 = ttab_s[b + 1];
                float t = fmaf(frac, t1 - t0, t0);
                t = (x > 0.0f) ? t : ((x < 0.0f) ? -t : 0.0f);
                Ts[row * 33 + lane] = t;
            }
        }
        // prefetch V chunk c+1 (uniform branch)
        if (c < 31) {
            const float* vp = vrow_ptr + (size_t)(c + 1) * 32 * HD;
            vv0 = *(const float4*)vp;
            vv1 = *(const float4*)(vp + 4);
        }
        __syncthreads();
        // math: rows ty*4..+4, cols tx*8..+8; also row |sums| from Ts reads
        #pragma unroll 8
        for (int k = 0; k < 32; k++) {
            unsigned a0 = (unsigned)k * 256u + (unsigned)tx * 32u;
            float4 b0 = *(const float4*)&Vs[sw(a0) >> 2];
            float4 b1 = *(const float4*)&Vs[sw(a0 + 16u) >> 2];
            ull bv0 = pack2(b0.x, b0.y), bv1 = pack2(b0.z, b0.w);
            ull bv2 = pack2(b1.x, b1.y), bv3 = pack2(b1.z, b1.w);
            #pragma unroll
            for (int ii = 0; ii < 4; ii++) {
                float av = Ts[(ty * 4 + ii) * 33 + k];  // 4 distinct banks, bcast
                srow4[ii] += fabsf(av);
                ull a2 = pack2(av, av);
                acc[ii][0] = fma2(a2, bv0, acc[ii][0]);
                acc[ii][1] = fma2(a2, bv1, acc[ii][1]);
                acc[ii][2] = fma2(a2, bv2, acc[ii][2]);
                acc[ii][3] = fma2(a2, bv3, acc[ii][3]);
            }
        }
    }

    // tx==0 threads own the (duplicated) row sums
    if (tx == 0) {
        #pragma unroll
        for (int ii = 0; ii < 4; ii++)
            sinv[ty * 4 + ii] = 1.0f / srow4[ii];
    }
    __syncthreads();

    int d0 = tx * 8;
    #pragma unroll
    for (int ii = 0; ii < 4; ii++) {
        int lrow = ty * 4 + ii;
        float s = sinv[lrow];
        float2 c0 = unpack2(acc[ii][0]);
        float2 c1 = unpack2(acc[ii][1]);
        float2 c2 = unpack2(acc[ii][2]);
        float2 c3 = unpack2(acc[ii][3]);
        size_t oidx = (size_t)(i0 + lrow) * HD + d0;
        *(float4*)&O[oidx]     = make_float4(c0.x * s, c0.y * s, c1.x * s, c1.y * s);
        *(float4*)&O[oidx + 4] = make_float4(c2.x * s, c2.y * s, c3.x * s, c3.y * s);
    }
}

// ---------------- launcher ---------------------------------------------------
extern "C" void kernel_launch(void* const* d_in, const int* in_sizes, int n_in,
                              void* d_out, int out_size) {
    const float* Q = (const float*)d_in[0];
    const float* K = (const float*)d_in[1];
    const float* V = (const float*)d_in[2];
    float* O = (float*)d_out;

    norms_kernel<<<8192, 256>>>(Q, K);
    score_kernel<<<dim3(8, 8, NBH), 256>>>(Q, K);
    scan_ttab_kernel<<<1, 1024>>>();
    out_kernel<<<256, 256>>>(V, O);
}

// round 15
// speedup vs baseline: 1.5252x; 1.0557x over previous
#include <cuda_runtime.h>
#include <cstdint>
#include <math.h>

// Problem shape (fixed): B=4, H=8, S=1024, D=64
#define SLEN 1024
#define HD   64
#define NBH  32
#define NROWS (NBH * SLEN)           // 32768
#define NTOT  ((size_t)NROWS * SLEN) // 33554432 = 2^25
#define NBINS 4096                   // bits >> 18 : 8 exp + 5 mantissa bits
#define KSPLIT 4

typedef unsigned long long ull;

// ---------------- scratch ---------------------------------------------------
__device__ float g_score[NROWS * SLEN];          // 128 MiB raw scores
__device__ unsigned int g_hist[NBINS];           // 16 KiB counts
__device__ float g_ttab[NBINS + 1];              // edge t values
__device__ float g_invq[NROWS];
__device__ float g_invk[NROWS];
__device__ float g_pout[KSPLIT * NROWS * HD];    // 32 MiB partial outputs
__device__ float g_psum[KSPLIT * NROWS];         // partial row |sums|

// ---------------- f32x2 helpers (sm_103a) -----------------------------------
__device__ __forceinline__ ull pack2(float a, float b) {
    ull r; asm("mov.b64 %0, {%1,%2};" : "=l"(r) : "f"(a), "f"(b)); return r;
}
__device__ __forceinline__ ull fma2(ull a, ull b, ull c) {
    ull d; asm("fma.rn.f32x2 %0, %1, %2, %3;" : "=l"(d) : "l"(a), "l"(b), "l"(c));
    return d;
}
__device__ __forceinline__ float2 unpack2(ull v) {
    float2 f; asm("mov.b64 {%0,%1}, %2;" : "=f"(f.x), "=f"(f.y) : "l"(v));
    return f;
}
__device__ __forceinline__ unsigned sw(unsigned a) {      // 128B-line swizzle
    return a ^ ((a >> 3) & 0x70u);
}

// ---------------- kernel 1: inverse row norms (+ hist zeroing) --------------
__global__ __launch_bounds__(256) void norms_kernel(const float* __restrict__ Q,
                                                    const float* __restrict__ K) {
    if (blockIdx.x < 16) g_hist[blockIdx.x * 256 + threadIdx.x] = 0u;
    int w = (blockIdx.x * 256 + threadIdx.x) >> 5;
    int lane = threadIdx.x & 31;
    const float* src; float* dst; int row;
    if (w < NROWS) { src = Q; dst = g_invq; row = w; }
    else           { src = K; dst = g_invk; row = w - NROWS; }
    const float* p = src + (size_t)row * HD;
    float a = p[lane], b = p[lane + 32];
    float s = a * a + b * b;
    #pragma unroll
    for (int o = 16; o; o >>= 1) s += __shfl_xor_sync(0xffffffffu, s, o);
    if (lane == 0) dst[row] = 1.0f / (sqrtf(s) + 1e-5f);
}

// ---------------- kernel 2: score GEMM + smem-private histogram -------------
__global__ __launch_bounds__(256, 2) void score_kernel(const float* __restrict__ Q,
                                                       const float* __restrict__ K) {
    __shared__ __align__(16) float Qsk[32 * 132];  // [k][row] (hist0 alias)
    __shared__ __align__(16) float Ks[32 * 128];   // k-major SW128 (hist1 alias)
    int bh = blockIdx.z;
    int i0 = blockIdx.y * 128, j0 = blockIdx.x * 128;
    const float* Qb = Q + (size_t)bh * SLEN * HD;
    const float* Kb = K + (size_t)bh * SLEN * HD;
    int tid = threadIdx.x;
    int tx = tid & 15, ty = tid >> 4;

    ull acc[8][4];
    #pragma unroll
    for (int ii = 0; ii < 8; ii++)
        #pragma unroll
        for (int p = 0; p < 4; p++) acc[ii][p] = 0ull;

    #pragma unroll
    for (int c = 0; c < 2; c++) {          // k chunks of 32 (ascending order!)
        int k0 = c * 32;
        if (c) __syncthreads();
        #pragma unroll
        for (int pass = 0; pass < 4; pass++) {
            int row = (tid >> 3) + pass * 32;
            int kq = (tid & 7) * 4;
            float4 q4 = *(const float4*)&Qb[(i0 + row) * HD + k0 + kq];
            Qsk[(kq + 0) * 132 + row] = q4.x;
            Qsk[(kq + 1) * 132 + row] = q4.y;
            Qsk[(kq + 2) * 132 + row] = q4.z;
            Qsk[(kq + 3) * 132 + row] = q4.w;
            float4 k4 = *(const float4*)&Kb[(j0 + row) * HD + k0 + kq];
            #pragma unroll
            for (int e = 0; e < 4; e++) {
                unsigned a = (unsigned)(kq + e) * 512u + (unsigned)row * 4u;
                Ks[sw(a) >> 2] = (&k4.x)[e];
            }
        }
        __syncthreads();
        #pragma unroll
        for (int k = 0; k < 32; k++) {
            unsigned a0 = (unsigned)k * 512u + (unsigned)tx * 32u;
            float4 b0 = *(const float4*)&Ks[sw(a0) >> 2];
            float4 b1 = *(const float4*)&Ks[sw(a0 + 16u) >> 2];
            ull bv0 = pack2(b0.x, b0.y), bv1 = pack2(b0.z, b0.w);
            ull bv2 = pack2(b1.x, b1.y), bv3 = pack2(b1.z, b1.w);
            float4 av0 = *(const float4*)&Qsk[k * 132 + ty * 8];
            float4 av1 = *(const float4*)&Qsk[k * 132 + ty * 8 + 4];
            const float* avp0 = &av0.x;
            const float* avp1 = &av1.x;
            #pragma unroll
            for (int ii = 0; ii < 4; ii++) {
                ull a2 = pack2(avp0[ii], avp0[ii]);
                acc[ii][0] = fma2(a2, bv0, acc[ii][0]);
                acc[ii][1] = fma2(a2, bv1, acc[ii][1]);
                acc[ii][2] = fma2(a2, bv2, acc[ii][2]);
                acc[ii][3] = fma2(a2, bv3, acc[ii][3]);
            }
            #pragma unroll
            for (int ii = 0; ii < 4; ii++) {
                ull a2 = pack2(avp1[ii], avp1[ii]);
                acc[4 + ii][0] = fma2(a2, bv0, acc[4 + ii][0]);
                acc[4 + ii][1] = fma2(a2, bv1, acc[4 + ii][1]);
                acc[4 + ii][2] = fma2(a2, bv2, acc[4 + ii][2]);
                acc[4 + ii][3] = fma2(a2, bv3, acc[4 + ii][3]);
            }
        }
    }

    // ---- epilogue: tiles dead; alias as two u16-packed lane-parity subhists --
    unsigned* hist0 = (unsigned*)Qsk;     // 2048 u32 = 4096 u16 counters
    unsigned* hist1 = (unsigned*)Ks;      // 2048 u32
    __syncthreads();
    for (int i = tid; i < 2048; i += 256) { hist0[i] = 0u; hist1[i] = 0u; }
    __syncthreads();
    unsigned* hsel = (tid & 1) ? hist1 : hist0;

    int jb = j0 + tx * 8;
    float ikv[8];
    #pragma unroll
    for (int jj = 0; jj < 8; jj++) ikv[jj] = g_invk[bh * SLEN + jb + jj];
    #pragma unroll
    for (int ii = 0; ii < 8; ii++) {
        int row = bh * SLEN + i0 + ty * 8 + ii;
        float iq = g_invq[row];
        float2 c0 = unpack2(acc[ii][0]);
        float2 c1 = unpack2(acc[ii][1]);
        float2 c2 = unpack2(acc[ii][2]);
        float2 c3 = unpack2(acc[ii][3]);
        float v[8];
        v[0] = c0.x * iq * ikv[0]; v[1] = c0.y * iq * ikv[1];
        v[2] = c1.x * iq * ikv[2]; v[3] = c1.y * iq * ikv[3];
        v[4] = c2.x * iq * ikv[4]; v[5] = c2.y * iq * ikv[5];
        v[6] = c3.x * iq * ikv[6]; v[7] = c3.y * iq * ikv[7];
        size_t idx = (size_t)row * SLEN + jb;
        *(float4*)&g_score[idx]     = make_float4(v[0], v[1], v[2], v[3]);
        *(float4*)&g_score[idx + 4] = make_float4(v[4], v[5], v[6], v[7]);
        #pragma unroll
        for (int e = 0; e < 8; e++) {
            unsigned bin = __float_as_uint(fabsf(v[e])) >> 18;   // < 4096
            atomicAdd(&hsel[bin >> 1], 1u << ((bin & 1u) * 16u));
        }
    }

    __syncthreads();
    for (int i = tid; i < 2048; i += 256) {
        unsigned p0 = hist0[i], p1 = hist1[i];
        unsigned lo = (p0 & 0xFFFFu) + (p1 & 0xFFFFu);
        unsigned hi = (p0 >> 16) + (p1 >> 16);
        if (lo) atomicAdd(&g_hist[2 * i],     lo);
        if (hi) atomicAdd(&g_hist[2 * i + 1], hi);
    }
}

// ---------------- kernel 2.5: scan 4096 bins + edge t table (1 block) -------
__global__ __launch_bounds__(1024) void scan_ttab_kernel() {
    __shared__ unsigned ws[32];
    int tid = threadIdx.x;
    int lane = tid & 31, wid = tid >> 5;
    unsigned c0 = g_hist[tid * 4], c1 = g_hist[tid * 4 + 1];
    unsigned c2 = g_hist[tid * 4 + 2], c3 = g_hist[tid * 4 + 3];
    unsigned tsum = c0 + c1 + c2 + c3;
    unsigned incl = tsum;
    #pragma unroll
    for (int o = 1; o < 32; o <<= 1) {
        unsigned n = __shfl_up_sync(0xffffffffu, incl, o);
        if (lane >= o) incl += n;
    }
    if (lane == 31) ws[wid] = incl;
    __syncthreads();
    if (wid == 0) {
        unsigned v = ws[lane];
        #pragma unroll
        for (int o = 1; o < 32; o <<= 1) {
            unsigned n = __shfl_up_sync(0xffffffffu, v, o);
            if (lane >= o) v += n;
        }
        ws[lane] = v;
    }
    __syncthreads();
    unsigned excl = incl - tsum + (wid ? ws[wid - 1] : 0u);
    const float sA = 1.0f / 33554431.0f;   // 1/(n-1)
    const float sB = 1.0f / 33554432.0f;   // 1/n
    unsigned e0 = excl, e1 = e0 + c0, e2 = e1 + c1, e3 = e2 + c2;
    g_ttab[tid * 4]     = -__logf(fmaf((float)e0, sA, sB));
    g_ttab[tid * 4 + 1] = -__logf(fmaf((float)e1, sA, sB));
    g_ttab[tid * 4 + 2] = -__logf(fmaf((float)e2, sA, sB));
    g_ttab[tid * 4 + 3] = -__logf(fmaf((float)e3, sA, sB));
    if (tid == 1023)
        g_ttab[4096] = -__logf(fmaf((float)(e3 + c3), sA, sB));
}

// ---------------- kernel 3: fused transform + partial out GEMM ---------------
// 1024 blocks = 256 row-groups x 4 k-splits. Each block: 128 rows x 256 k-cols
// (8 chunks of 32). Partial O and partial row |sums| go to global scratch;
// fixup_kernel combines. Fine-grained grid sustains 3 blocks/SM.
__global__ __launch_bounds__(256, 3) void out_kernel(const float* __restrict__ V) {
    __shared__ float Ts[128 * 33];       // [row][k] (16.5 KB)
    __shared__ float Vs[32 * 64];        // [k][d] SW128 (8 KB)
    __shared__ float ttab_s[NBINS + 1];  // 16.4 KB

    int blk = blockIdx.x;                // 0..1023
    int ks = blk & 3;                    // k-split index
    int rg = blk >> 2;                   // row group 0..255
    int bh = rg >> 3;
    int i0 = rg * 128;
    int kbase = ks * 256;                // first k col of this split
    const float* Vb = V + (size_t)bh * SLEN * HD;
    int tid = threadIdx.x;
    int tx = tid & 7, ty = tid >> 3;     // math: 8 col-groups x 32 row-groups
    int lane = tid & 31, wrp = tid >> 5;
    int kv = tid >> 3, d8 = (tid & 7) * 8;   // V staging map

    for (int i = tid; i < NBINS + 1; i += 256) ttab_s[i] = g_ttab[i];
    __syncthreads();

    ull acc[4][4];
    #pragma unroll
    for (int ii = 0; ii < 4; ii++)
        #pragma unroll
        for (int p = 0; p < 4; p++) acc[ii][p] = 0ull;
    float srow4[4] = {0.0f, 0.0f, 0.0f, 0.0f};

    const float* pbase = g_score + (size_t)i0 * SLEN + kbase + lane;
    const float* vrow_ptr = &Vb[(kbase + kv) * HD + d8];

    // prefetch V chunk 0
    float4 vv0 = *(const float4*)vrow_ptr;
    float4 vv1 = *(const float4*)(vrow_ptr + 4);

    for (int c = 0; c < 8; c++) {
        if (c) __syncthreads();          // previous math done before overwrite
        // consume prefetched V -> Vs (swizzled)
        {
            unsigned a = (unsigned)kv * 256u + (unsigned)d8 * 4u;
            *(float4*)&Vs[sw(a) >> 2]       = vv0;
            *(float4*)&Vs[sw(a + 16u) >> 2] = vv1;
        }
        // stage + transform P: rows wrp + r*8, col = kbase + c*32 + lane
        #pragma unroll
        for (int hb = 0; hb < 2; hb++) {
            float v[8];
            #pragma unroll
            for (int r = 0; r < 8; r++) {
                int row = wrp + (hb * 8 + r) * 8;
                v[r] = __ldg(pbase + (size_t)row * SLEN + c * 32);
            }
            #pragma unroll
            for (int r = 0; r < 8; r++) {
                int row = wrp + (hb * 8 + r) * 8;
                float x = v[r];
                unsigned bits = __float_as_uint(fabsf(x));
                unsigned b = bits >> 18;
                float frac = (float)(bits & 0x3FFFFu) * (1.0f / 262144.0f);
                float t0 = ttab_s[b], t1 = ttab_s[b + 1];
                float t = fmaf(frac, t1 - t0, t0);
                t = (x > 0.0f) ? t : ((x < 0.0f) ? -t : 0.0f);
                Ts[row * 33 + lane] = t;
            }
        }
        // prefetch V chunk c+1 (uniform branch)
        if (c < 7) {
            const float* vp = vrow_ptr + (size_t)(c + 1) * 32 * HD;
            vv0 = *(const float4*)vp;
            vv1 = *(const float4*)(vp + 4);
        }
        __syncthreads();
        // math: rows ty*4..+4, cols tx*8..+8; row |sums| from Ts reads
        #pragma unroll 8
        for (int k = 0; k < 32; k++) {
            unsigned a0 = (unsigned)k * 256u + (unsigned)tx * 32u;
            float4 b0 = *(const float4*)&Vs[sw(a0) >> 2];
            float4 b1 = *(const float4*)&Vs[sw(a0 + 16u) >> 2];
            ull bv0 = pack2(b0.x, b0.y), bv1 = pack2(b0.z, b0.w);
            ull bv2 = pack2(b1.x, b1.y), bv3 = pack2(b1.z, b1.w);
            #pragma unroll
            for (int ii = 0; ii < 4; ii++) {
                float av = Ts[(ty * 4 + ii) * 33 + k];  // 4 distinct banks, bcast
                srow4[ii] += fabsf(av);
                ull a2 = pack2(av, av);
                acc[ii][0] = fma2(a2, bv0, acc[ii][0]);
                acc[ii][1] = fma2(a2, bv1, acc[ii][1]);
                acc[ii][2] = fma2(a2, bv2, acc[ii][2]);
                acc[ii][3] = fma2(a2, bv3, acc[ii][3]);
            }
        }
    }

    // partial row sums (tx==0 owns; duplicated across tx)
    if (tx == 0) {
        #pragma unroll
        for (int ii = 0; ii < 4; ii++)
            g_psum[ks * NROWS + i0 + ty * 4 + ii] = srow4[ii];
    }

    // partial outputs
    float* pout = g_pout + (size_t)ks * NROWS * HD;
    int d0 = tx * 8;
    #pragma unroll
    for (int ii = 0; ii < 4; ii++) {
        int lrow = ty * 4 + ii;
        float2 c0 = unpack2(acc[ii][0]);
        float2 c1 = unpack2(acc[ii][1]);
        float2 c2 = unpack2(acc[ii][2]);
        float2 c3 = unpack2(acc[ii][3]);
        size_t oidx = (size_t)(i0 + lrow) * HD + d0;
        *(float4*)&pout[oidx]     = make_float4(c0.x, c0.y, c1.x, c1.y);
        *(float4*)&pout[oidx + 4] = make_float4(c2.x, c2.y, c3.x, c3.y);
    }
}

// ---------------- kernel 4: combine partials ---------------------------------
__global__ __launch_bounds__(256) void fixup_kernel(float* __restrict__ O) {
    int idx = blockIdx.x * 256 + threadIdx.x;   // 0 .. 2M-1
    int row = idx >> 6;
    float s = g_psum[row] + g_psum[NROWS + row] +
              g_psum[2 * NROWS + row] + g_psum[3 * NROWS + row];
    float o = g_pout[idx] + g_pout[NROWS * HD + idx] +
              g_pout[2 * NROWS * HD + idx] + g_pout[3 * NROWS * HD + idx];
    O[idx] = o * (1.0f / s);
}

// ---------------- launcher ---------------------------------------------------
extern "C" void kernel_launch(void* const* d_in, const int* in_sizes, int n_in,
                              void* d_out, int out_size) {
    const float* Q = (const float*)d_in[0];
    const float* K = (const float*)d_in[1];
    const float* V = (const float*)d_in[2];
    float* O = (float*)d_out;

    norms_kernel<<<8192, 256>>>(Q, K);
    score_kernel<<<dim3(8, 8, NBH), 256>>>(Q, K);
    scan_ttab_kernel<<<1, 1024>>>();
    out_kernel<<<1024, 256>>>(V);
    fixup_kernel<<<NROWS * HD / 256, 256>>>(O);
}